// round 13
// baseline (speedup 1.0000x reference)
#include <cuda_runtime.h>
#include <cuda_fp16.h>
#include <stdint.h>

// CapsuleLayer dynamic routing: recompute architecture, pipelined HMMA GEMMs.
// B=256, I=16, C=1152, U=10, S=32, J=320, K1=18432, 3 iterations.
// R13 = R12 + fused squash-in-g1 (grid spin barrier), fused bupd-in-g2,
//       merged prep. 6 launches total.

#define BB   256
#define CC   1152
#define NU   10
#define SS   32
#define JJ   320
#define K1   18432
#define SPLIT 48
#define KCHUNK 384          // K1/SPLIT
#define NSTG  12            // KCHUNK/32
#define G1STG 3             // pipeline depth
#define ASTR  40            // A smem stride (halfs)
#define BSTR  264           // B smem stride (halfs)
#define BSTR2 136           // G2 smem stride (halfs)
#define G1BLKS 240          // 5*48, co-resident at 2 CTA/SM (<=296)

// ---- static device scratch ----
__device__ __half d_xhT[(size_t)K1 * BB];            // 9.4 MB  [k][b]
__device__ __half d_WTh[(size_t)JJ * K1];            // 11.8 MB [j][k] fp16
__device__ __half d_spart[(size_t)SPLIT * JJ * BB];  // 7.9 MB fp16
__device__ float  d_s  [JJ * BB];                    // 327 KB reduced s
__device__ __half d_vh [JJ * BB];                    // [j][b]
__device__ float  d_bij[CC * NU];
__device__ __half d_cijh[NU * CC];                   // [u][c] fp16
__device__ float  d_A2 [CC * NU];
__device__ int    d_cnt1;                            // g1 grid barrier
__device__ int    d_cnt2;                            // g2 last-block ticket

// ---- helpers ----
__device__ __forceinline__ void mma16816(float* d, uint32_t a0, uint32_t a1,
                                         uint32_t a2, uint32_t a3,
                                         uint32_t b0, uint32_t b1) {
    asm volatile(
        "mma.sync.aligned.m16n8k16.row.col.f32.f16.f16.f32 "
        "{%0,%1,%2,%3},{%4,%5,%6,%7},{%8,%9},{%0,%1,%2,%3};"
        : "+f"(d[0]), "+f"(d[1]), "+f"(d[2]), "+f"(d[3])
        : "r"(a0), "r"(a1), "r"(a2), "r"(a3), "r"(b0), "r"(b1));
}
__device__ __forceinline__ uint32_t cvta_s(const void* p) {
    return (uint32_t)__cvta_generic_to_shared(p);
}
__device__ __forceinline__ void ldsm_x4(uint32_t* r, uint32_t addr) {
    asm volatile("ldmatrix.sync.aligned.m8n8.x4.shared.b16 {%0,%1,%2,%3},[%4];"
                 : "=r"(r[0]), "=r"(r[1]), "=r"(r[2]), "=r"(r[3]) : "r"(addr));
}
__device__ __forceinline__ void ldsm_x4_t(uint32_t* r, uint32_t addr) {
    asm volatile("ldmatrix.sync.aligned.m8n8.x4.trans.shared.b16 {%0,%1,%2,%3},[%4];"
                 : "=r"(r[0]), "=r"(r[1]), "=r"(r[2]), "=r"(r[3]) : "r"(addr));
}
__device__ __forceinline__ uint32_t h2u(__half2 h) {
    return *reinterpret_cast<uint32_t*>(&h);
}
__device__ __forceinline__ uint32_t hmul2u(uint32_t a, uint32_t b) {
    __half2 r = __hmul2(*reinterpret_cast<__half2*>(&a), *reinterpret_cast<__half2*>(&b));
    return h2u(r);
}
__device__ __forceinline__ void cp16(uint32_t dst, const void* src) {
    asm volatile("cp.async.cg.shared.global [%0], [%1], 16;" :: "r"(dst), "l"(src));
}
__device__ __forceinline__ void cp_commit() { asm volatile("cp.async.commit_group;"); }
__device__ __forceinline__ void cp_wait0() { asm volatile("cp.async.wait_group 0;"); }
__device__ __forceinline__ void cp_wait1() { asm volatile("cp.async.wait_group 1;"); }

// ---------------------------------------------------------------------------
// merged prep: blocks [0, 4608) transpose x; [4608, 10368) transpose W.
// block 0 also inits routing state + barrier counters.
#define PREP_XBLKS (576 * 8)
#define PREP_WBLKS (160 * 36)
__global__ void k_prep(const float* __restrict__ x, const float* __restrict__ W) {
    __shared__ float t32[32][33];
    int tx = threadIdx.x, ty = threadIdx.y;
    int id = blockIdx.x;
    if (id == 0) {
        int tid = ty * 32 + tx;
        for (int t = tid; t < CC * NU; t += 256) {
            d_bij[t] = 0.f; d_A2[t] = 0.f;
            d_cijh[t] = __float2half(0.1f);
        }
        if (tid == 0) { d_cnt1 = 0; d_cnt2 = 0; }
    }
    if (id < PREP_XBLKS) {
        int k0 = (id % 576) * 32, b0 = (id / 576) * 32;
        #pragma unroll
        for (int i = 0; i < 4; i++)
            t32[ty + i * 8][tx] = x[(size_t)(b0 + ty + i * 8) * K1 + k0 + tx];
        __syncthreads();
        #pragma unroll
        for (int i = 0; i < 4; i++) {
            int k = k0 + ty + i * 8;
            d_xhT[(size_t)k * BB + b0 + tx] = __float2half(t32[tx][ty + i * 8]);
        }
    } else {
        int wid2 = id - PREP_XBLKS;
        int m0 = (wid2 % 160) * 32, c0 = (wid2 / 160) * 32;
        #pragma unroll
        for (int i = 0; i < 4; i++)
            t32[ty + i * 8][tx] = W[(size_t)(c0 + ty + i * 8) * 5120 + m0 + tx];
        __syncthreads();
        #pragma unroll
        for (int i = 0; i < 4; i++) {
            int m = m0 + ty + i * 8;
            int j = m >> 4, ii = m & 15;
            d_WTh[(size_t)j * K1 + ii * CC + c0 + tx] = __float2half(t32[tx][ty + i * 8]);
        }
    }
}

// ---------------------------------------------------------------------------
// G1 + fused squash. grid (5 j-tiles of 64, 48 splits) = 240 blocks.
// Main GEMM writes spart; grid barrier; Phase A reduces 48->1 into d_s (L2-hot);
// barrier; Phase B (first 32 blocks) squashes and writes vh / out.
__global__ void __launch_bounds__(256, 2) k_g1(float* __restrict__ out,
                                               int base, int final_it) {
    extern __shared__ __align__(16) __half sm1[];
    __half* a_s = sm1;                         // [G1STG][64*ASTR]
    __half* b_s = sm1 + G1STG * 64 * ASTR;     // [G1STG][32*BSTR]

    const int tid = threadIdx.x;
    const int j0 = blockIdx.x * 64;
    const int kbase = blockIdx.y * KCHUNK;
    const int warp = tid >> 5, lane = tid & 31;
    const int wm = warp >> 2, wn = warp & 3;
    const int m0 = wm * 32, n0 = wn * 64;
    const int lt = lane >> 3, lr = lane & 7;
    const int g = lane >> 2, t = lane & 3;

    const int u_w = (j0 >> 5) + wm;
    const __half* crow = d_cijh + u_w * CC;
    const int c0base = kbase % CC;

    const int ar = tid >> 2, aq = tid & 3;
    const __half* wrow = d_WTh + (size_t)(j0 + ar) * K1;

    const uint32_t aoff = (uint32_t)((((lt & 1) * 8 + lr) * ASTR + (lt >> 1) * 8) * 2);
    const uint32_t boff = (uint32_t)((((lt & 1) * 8 + lr) * BSTR + (lt >> 1) * 8) * 2);
    uint32_t abase[G1STG], bbase[G1STG];
    #pragma unroll
    for (int i = 0; i < G1STG; i++) {
        abase[i] = cvta_s(a_s + i * 64 * ASTR);
        bbase[i] = cvta_s(b_s + i * 32 * BSTR);
    }

    float acc[16][4];
    #pragma unroll
    for (int nb = 0; nb < 16; nb++)
        #pragma unroll
        for (int q = 0; q < 4; q++) acc[nb][q] = 0.f;

    auto issue = [&](int s) {
        int k0 = kbase + s * 32;
        int buf = s % G1STG;
        cp16(abase[buf] + (uint32_t)((ar * ASTR + aq * 8) * 2), wrow + k0 + aq * 8);
        #pragma unroll
        for (int i = 0; i < 4; i++) {
            int idx = tid + i * 256;
            int r = idx >> 5, seg = idx & 31;
            cp16(bbase[buf] + (uint32_t)((r * BSTR + seg * 8) * 2),
                 d_xhT + (size_t)(k0 + r) * BB + seg * 8);
        }
        cp_commit();
    };

    issue(0);
    issue(1);
    cp_wait1();
    __syncthreads();

    for (int s = 0; s < NSTG; s++) {
        int buf = s % G1STG;
        if (s + 2 < NSTG) issue(s + 2);

        #pragma unroll
        for (int kk = 0; kk < 32; kk += 16) {
            int cidx = c0base + s * 32 + kk;
            uint32_t cl = *(const uint32_t*)(crow + cidx + 2 * t);
            uint32_t ch = *(const uint32_t*)(crow + cidx + 8 + 2 * t);
            uint32_t A0[4], A1[4], rr[4];
            ldsm_x4(A0, abase[buf] + (uint32_t)((m0 * ASTR + kk) * 2) + aoff);
            ldsm_x4(A1, abase[buf] + (uint32_t)(((m0 + 16) * ASTR + kk) * 2) + aoff);
            A0[0] = hmul2u(A0[0], cl); A0[1] = hmul2u(A0[1], cl);
            A0[2] = hmul2u(A0[2], ch); A0[3] = hmul2u(A0[3], ch);
            A1[0] = hmul2u(A1[0], cl); A1[1] = hmul2u(A1[1], cl);
            A1[2] = hmul2u(A1[2], ch); A1[3] = hmul2u(A1[3], ch);
            #pragma unroll
            for (int i = 0; i < 4; i++) {
                ldsm_x4_t(rr, bbase[buf] + (uint32_t)((kk * BSTR + n0 + i * 16) * 2) + boff);
                mma16816(acc[2 * i],     A0[0], A0[1], A0[2], A0[3], rr[0], rr[1]);
                mma16816(acc[2 * i + 1], A0[0], A0[1], A0[2], A0[3], rr[2], rr[3]);
                mma16816(acc[8 + 2 * i],     A1[0], A1[1], A1[2], A1[3], rr[0], rr[1]);
                mma16816(acc[8 + 2 * i + 1], A1[0], A1[1], A1[2], A1[3], rr[2], rr[3]);
            }
        }
        if (s + 2 < NSTG) cp_wait1(); else cp_wait0();
        __syncthreads();
    }

    size_t sbase = (size_t)blockIdx.y * JJ * BB;
    #pragma unroll
    for (int mb = 0; mb < 2; mb++) {
        int j = j0 + m0 + mb * 16 + g;
        #pragma unroll
        for (int nb = 0; nb < 8; nb++) {
            float* a = acc[mb * 8 + nb];
            int b = n0 + nb * 8 + 2 * t;
            *(__half2*)&d_spart[sbase + (size_t)j * BB + b] = __floats2half2_rn(a[0], a[1]);
            *(__half2*)&d_spart[sbase + (size_t)(j + 8) * BB + b] = __floats2half2_rn(a[2], a[3]);
        }
    }

    // ---- grid barrier 1: all spart written ----
    const int gbid = blockIdx.y * 5 + blockIdx.x;
    const int gid = gbid * 256 + tid;
    __threadfence();
    __syncthreads();
    if (tid == 0) {
        atomicAdd(&d_cnt1, 1);
        while (*((volatile int*)&d_cnt1) < base + G1BLKS) {}
    }
    __syncthreads();
    __threadfence();

    // ---- Phase A: reduce 48 partials (L2-hot) into d_s ----
    for (int idx = gid; idx < JJ * BB; idx += G1BLKS * 256) {
        float v = 0.f;
        #pragma unroll
        for (int p = 0; p < SPLIT; p++)
            v += __half2float(d_spart[(size_t)p * JJ * BB + idx]);
        d_s[idx] = v;
    }

    // ---- grid barrier 2: d_s complete ----
    __threadfence();
    __syncthreads();
    if (tid == 0) {
        atomicAdd(&d_cnt1, 1);
        if (gbid < 32) {
            while (*((volatile int*)&d_cnt1) < base + 2 * G1BLKS) {}
        }
    }
    __syncthreads();
    if (gbid >= 32) return;          // not needed for Phase B
    __threadfence();

    // ---- Phase B: squash (first 32 blocks = 8192 (s,b) items) ----
    {
        int s = gid >> 8, b = gid & 255;
        float sv[NU], q = 0.f;
        #pragma unroll
        for (int u = 0; u < NU; u++) {
            float v = d_s[(u * 32 + s) * BB + b];
            sv[u] = v;
            q = fmaf(v, v, q);
        }
        float mag = sqrtf(q);
        float f = q / ((1.f + q) * mag);
        #pragma unroll
        for (int u = 0; u < NU; u++) {
            float v = sv[u] * f;
            int j = u * 32 + s;
            if (final_it) out[b * JJ + j] = v;
            else          d_vh[j * BB + b] = __float2half(v);
        }
    }
}

// ---------------------------------------------------------------------------
// G2 + fused bupd: A2[c,u] += sum_j W[j,k'] * (sum_b vh[j,b]*x[k',b]);
// last block (ticket) does b_ij update + softmax -> cij.
__global__ void __launch_bounds__(256, 3) k_g2() {
    extern __shared__ __align__(16) __half sm2[];
    __half* xs = sm2;                      // [128][BSTR2]
    __half* vs = sm2 + 128 * BSTR2;        // [2][32][BSTR2]

    const int tid = threadIdx.x, warp = tid >> 5, lane = tid & 31;
    const int wm = warp >> 2, wn = warp & 3;
    const int lt = lane >> 3, lr = lane & 7;
    const int g = lane >> 2, t = lane & 3;
    const int kp0 = blockIdx.x * 128;
    const int b0 = blockIdx.y * 128;
    const int cb = kp0 % CC;

    const uint32_t xbase = cvta_s(xs);
    uint32_t vbase[2] = {cvta_s(vs), cvta_s(vs + 32 * BSTR2)};

    auto issueV = [&](int u, int buf) {
        #pragma unroll
        for (int i = 0; i < 2; i++) {
            int idx = tid + i * 256;
            int r = idx >> 4, seg = idx & 15;
            cp16(vbase[buf] + (uint32_t)((r * BSTR2 + seg * 8) * 2),
                 d_vh + (size_t)(u * 32 + r) * BB + b0 + seg * 8);
        }
        cp_commit();
    };

    #pragma unroll
    for (int i = 0; i < 8; i++) {
        int idx = tid + i * 256;
        int r = idx >> 4, seg = idx & 15;
        cp16(xbase + (uint32_t)((r * BSTR2 + seg * 8) * 2),
             d_xhT + (size_t)(kp0 + r) * BB + b0 + seg * 8);
    }
    issueV(0, 0);
    cp_wait0();
    __syncthreads();

    const uint32_t aoff = (uint32_t)(((wm * 16 + (lt & 1) * 8 + lr) * BSTR2 + (lt >> 1) * 8) * 2);
    const uint32_t boffc = (uint32_t)((((lt >> 1) * 8 + lr) * BSTR2 + (lt & 1) * 8) * 2);

    for (int u = 0; u < NU; u++) {
        int buf = u & 1;
        if (u + 1 < NU) issueV(u + 1, buf ^ 1);

        float acc[4][4];
        #pragma unroll
        for (int nb = 0; nb < 4; nb++)
            #pragma unroll
            for (int q = 0; q < 4; q++) acc[nb][q] = 0.f;

        #pragma unroll
        for (int kk = 0; kk < 128; kk += 16) {
            uint32_t A[4], rr[4];
            ldsm_x4(A, vbase[buf] + (uint32_t)(kk * 2) + aoff);
            #pragma unroll
            for (int q = 0; q < 2; q++) {
                ldsm_x4(rr, xbase + (uint32_t)(((wn * 32 + q * 16) * BSTR2 + kk) * 2) + boffc);
                mma16816(acc[2 * q],     A[0], A[1], A[2], A[3], rr[0], rr[1]);
                mma16816(acc[2 * q + 1], A[0], A[1], A[2], A[3], rr[2], rr[3]);
            }
        }

        int jA = u * 32 + wm * 16 + g;
        const __half* wrow = d_WTh + (size_t)jA * K1;
        #pragma unroll
        for (int nb = 0; nb < 4; nb++) {
            int kc = kp0 + wn * 32 + nb * 8 + 2 * t;
            float2 w0 = __half22float2(*(const __half2*)(wrow + kc));
            float2 w1 = __half22float2(*(const __half2*)(wrow + 8 * (size_t)K1 + kc));
            float p0 = acc[nb][0] * w0.x + acc[nb][2] * w1.x;
            float p1 = acc[nb][1] * w0.y + acc[nb][3] * w1.y;
            #pragma unroll
            for (int m = 4; m <= 16; m <<= 1) {
                p0 += __shfl_xor_sync(0xffffffffu, p0, m);
                p1 += __shfl_xor_sync(0xffffffffu, p1, m);
            }
            if (g == 0) {
                int cc = cb + wn * 32 + nb * 8 + 2 * t;
                atomicAdd(&d_A2[cc * NU + u], p0);
                atomicAdd(&d_A2[(cc + 1) * NU + u], p1);
            }
        }
        if (u + 1 < NU) cp_wait0();
        __syncthreads();
    }

    // ---- fused b_ij update + softmax (last block) ----
    __shared__ int is_last;
    __threadfence();
    __syncthreads();
    if (tid == 0) {
        int old = atomicAdd(&d_cnt2, 1);
        is_last = (old == 287);          // grid = 144 x 2
    }
    __syncthreads();
    if (is_last) {
        if (tid == 0) d_cnt2 = 0;
        __threadfence();
        for (int c = tid; c < CC; c += 256) {
            float bv[NU], m = -1e30f;
            #pragma unroll
            for (int u = 0; u < NU; u++) {
                float a = d_A2[c * NU + u];
                d_A2[c * NU + u] = 0.f;
                float nb = d_bij[c * NU + u] + a * (1.f / BB);
                d_bij[c * NU + u] = nb;
                bv[u] = nb;
                m = fmaxf(m, nb);
            }
            float den = 0.f;
            #pragma unroll
            for (int u = 0; u < NU; u++) { bv[u] = expf(bv[u] - m); den += bv[u]; }
            float inv = 1.f / den;
            #pragma unroll
            for (int u = 0; u < NU; u++) d_cijh[u * CC + c] = __float2half(bv[u] * inv);
        }
    }
}

// ---------------------------------------------------------------------------
#define G1_SMEM ((G1STG * 64 * ASTR + G1STG * 32 * BSTR) * 2)   // 66048
#define G2_SMEM ((128 * BSTR2 + 64 * BSTR2) * 2)                // 52224

extern "C" void kernel_launch(void* const* d_in, const int* in_sizes, int n_in,
                              void* d_out, int out_size) {
    const float* x = (const float*)d_in[0];
    const float* W = (const float*)d_in[1];
    if (n_in >= 2 && in_sizes[0] == CC * NU * SS * 16 && in_sizes[1] == BB * 16 * CC) {
        const float* tmp = x; x = W; W = tmp;
    }
    float* out = (float*)d_out;

    static int attr_done = 0;
    if (!attr_done) {
        cudaFuncSetAttribute(k_g1, cudaFuncAttributeMaxDynamicSharedMemorySize, G1_SMEM);
        cudaFuncSetAttribute(k_g2, cudaFuncAttributeMaxDynamicSharedMemorySize, G2_SMEM);
        attr_done = 1;
    }

    k_prep<<<PREP_XBLKS + PREP_WBLKS, dim3(32, 8)>>>(x, W);

    for (int it = 0; it < 3; it++) {
        k_g1<<<dim3(5, SPLIT), 256, G1_SMEM>>>(out, it * 2 * G1BLKS, it == 2);
        if (it < 2) {
            k_g2<<<dim3(K1 / 128, 2), 256, G2_SMEM>>>();
        }
    }
}

// round 14
// speedup vs baseline: 1.3699x; 1.3699x over previous
#include <cuda_runtime.h>
#include <cuda_fp16.h>
#include <stdint.h>

// CapsuleLayer dynamic routing: recompute architecture, pipelined HMMA GEMMs.
// B=256, I=16, C=1152, U=10, S=32, J=320, K1=18432, 3 iterations.
// R14 = R12 (proven 133.6us) + merged prep + g2 W-epilogue prefetch.

#define BB   256
#define CC   1152
#define NU   10
#define SS   32
#define JJ   320
#define K1   18432
#define SPLIT 48
#define KCHUNK 384          // K1/SPLIT
#define NSTG  12            // KCHUNK/32
#define G1STG 3             // pipeline depth
#define ASTR  40            // A smem stride (halfs)
#define BSTR  264           // B smem stride (halfs)
#define BSTR2 136           // G2 smem stride (halfs)

// ---- static device scratch ----
__device__ __half d_xhT[(size_t)K1 * BB];            // 9.4 MB  [k][b]
__device__ __half d_WTh[(size_t)JJ * K1];            // 11.8 MB [j][k] fp16, k=i*1152+c
__device__ __half d_spart[(size_t)SPLIT * JJ * BB];  // 7.9 MB fp16
__device__ __half d_vh [JJ * BB];                    // [j][b]
__device__ float  d_bij[CC * NU];
__device__ __half d_cijh[NU * CC];                   // [u][c] fp16
__device__ float  d_A2 [CC * NU];

// ---- helpers ----
__device__ __forceinline__ void mma16816(float* d, uint32_t a0, uint32_t a1,
                                         uint32_t a2, uint32_t a3,
                                         uint32_t b0, uint32_t b1) {
    asm volatile(
        "mma.sync.aligned.m16n8k16.row.col.f32.f16.f16.f32 "
        "{%0,%1,%2,%3},{%4,%5,%6,%7},{%8,%9},{%0,%1,%2,%3};"
        : "+f"(d[0]), "+f"(d[1]), "+f"(d[2]), "+f"(d[3])
        : "r"(a0), "r"(a1), "r"(a2), "r"(a3), "r"(b0), "r"(b1));
}
__device__ __forceinline__ uint32_t cvta_s(const void* p) {
    return (uint32_t)__cvta_generic_to_shared(p);
}
__device__ __forceinline__ void ldsm_x4(uint32_t* r, uint32_t addr) {
    asm volatile("ldmatrix.sync.aligned.m8n8.x4.shared.b16 {%0,%1,%2,%3},[%4];"
                 : "=r"(r[0]), "=r"(r[1]), "=r"(r[2]), "=r"(r[3]) : "r"(addr));
}
__device__ __forceinline__ void ldsm_x4_t(uint32_t* r, uint32_t addr) {
    asm volatile("ldmatrix.sync.aligned.m8n8.x4.trans.shared.b16 {%0,%1,%2,%3},[%4];"
                 : "=r"(r[0]), "=r"(r[1]), "=r"(r[2]), "=r"(r[3]) : "r"(addr));
}
__device__ __forceinline__ uint32_t h2u(__half2 h) {
    return *reinterpret_cast<uint32_t*>(&h);
}
__device__ __forceinline__ uint32_t hmul2u(uint32_t a, uint32_t b) {
    __half2 r = __hmul2(*reinterpret_cast<__half2*>(&a), *reinterpret_cast<__half2*>(&b));
    return h2u(r);
}
__device__ __forceinline__ void cp16(uint32_t dst, const void* src) {
    asm volatile("cp.async.cg.shared.global [%0], [%1], 16;" :: "r"(dst), "l"(src));
}
__device__ __forceinline__ void cp_commit() { asm volatile("cp.async.commit_group;"); }
__device__ __forceinline__ void cp_wait0() { asm volatile("cp.async.wait_group 0;"); }
__device__ __forceinline__ void cp_wait1() { asm volatile("cp.async.wait_group 1;"); }

// ---------------------------------------------------------------------------
// merged prep: blocks [0, 4608) transpose x; [4608, 10368) transpose W.
// block 0 also inits routing state.
#define PREP_XBLKS (576 * 8)
#define PREP_WBLKS (160 * 36)
__global__ void k_prep(const float* __restrict__ x, const float* __restrict__ W) {
    __shared__ float t32[32][33];
    int tx = threadIdx.x, ty = threadIdx.y;
    int id = blockIdx.x;
    if (id == 0) {
        int tid = ty * 32 + tx;
        for (int t = tid; t < CC * NU; t += 256) {
            d_bij[t] = 0.f; d_A2[t] = 0.f;
            d_cijh[t] = __float2half(0.1f);
        }
    }
    if (id < PREP_XBLKS) {
        int k0 = (id % 576) * 32, b0 = (id / 576) * 32;
        #pragma unroll
        for (int i = 0; i < 4; i++)
            t32[ty + i * 8][tx] = x[(size_t)(b0 + ty + i * 8) * K1 + k0 + tx];
        __syncthreads();
        #pragma unroll
        for (int i = 0; i < 4; i++) {
            int k = k0 + ty + i * 8;
            d_xhT[(size_t)k * BB + b0 + tx] = __float2half(t32[tx][ty + i * 8]);
        }
    } else {
        int wid2 = id - PREP_XBLKS;
        int m0 = (wid2 % 160) * 32, c0 = (wid2 / 160) * 32;
        #pragma unroll
        for (int i = 0; i < 4; i++)
            t32[ty + i * 8][tx] = W[(size_t)(c0 + ty + i * 8) * 5120 + m0 + tx];
        __syncthreads();
        #pragma unroll
        for (int i = 0; i < 4; i++) {
            int m = m0 + ty + i * 8;
            int j = m >> 4, ii = m & 15;
            d_WTh[(size_t)j * K1 + ii * CC + c0 + tx] = __float2half(t32[tx][ty + i * 8]);
        }
    }
}

// ---------------------------------------------------------------------------
// G1: spart[p][j][b] = sum_{k chunk} (cij[u(j),c(k)]*W[j,k]) * x[b,k]
// grid (5 j-tiles of 64, 48 splits) = 240 blocks, 2 CTA/SM.
__global__ void __launch_bounds__(256, 2) k_g1() {
    extern __shared__ __align__(16) __half sm1[];
    __half* a_s = sm1;                         // [G1STG][64*ASTR]
    __half* b_s = sm1 + G1STG * 64 * ASTR;     // [G1STG][32*BSTR]

    const int tid = threadIdx.x;
    const int j0 = blockIdx.x * 64;
    const int kbase = blockIdx.y * KCHUNK;
    const int warp = tid >> 5, lane = tid & 31;
    const int wm = warp >> 2, wn = warp & 3;
    const int m0 = wm * 32, n0 = wn * 64;
    const int lt = lane >> 3, lr = lane & 7;
    const int g = lane >> 2, t = lane & 3;

    const int u_w = (j0 >> 5) + wm;
    const __half* crow = d_cijh + u_w * CC;
    const int c0base = kbase % CC;

    const int ar = tid >> 2, aq = tid & 3;
    const __half* wrow = d_WTh + (size_t)(j0 + ar) * K1;

    const uint32_t aoff = (uint32_t)((((lt & 1) * 8 + lr) * ASTR + (lt >> 1) * 8) * 2);
    const uint32_t boff = (uint32_t)((((lt & 1) * 8 + lr) * BSTR + (lt >> 1) * 8) * 2);
    uint32_t abase[G1STG], bbase[G1STG];
    #pragma unroll
    for (int i = 0; i < G1STG; i++) {
        abase[i] = cvta_s(a_s + i * 64 * ASTR);
        bbase[i] = cvta_s(b_s + i * 32 * BSTR);
    }

    float acc[16][4];
    #pragma unroll
    for (int nb = 0; nb < 16; nb++)
        #pragma unroll
        for (int q = 0; q < 4; q++) acc[nb][q] = 0.f;

    auto issue = [&](int s) {
        int k0 = kbase + s * 32;
        int buf = s % G1STG;
        cp16(abase[buf] + (uint32_t)((ar * ASTR + aq * 8) * 2), wrow + k0 + aq * 8);
        #pragma unroll
        for (int i = 0; i < 4; i++) {
            int idx = tid + i * 256;
            int r = idx >> 5, seg = idx & 31;
            cp16(bbase[buf] + (uint32_t)((r * BSTR + seg * 8) * 2),
                 d_xhT + (size_t)(k0 + r) * BB + seg * 8);
        }
        cp_commit();
    };

    issue(0);
    issue(1);
    cp_wait1();
    __syncthreads();

    for (int s = 0; s < NSTG; s++) {
        int buf = s % G1STG;
        if (s + 2 < NSTG) issue(s + 2);

        #pragma unroll
        for (int kk = 0; kk < 32; kk += 16) {
            int cidx = c0base + s * 32 + kk;
            uint32_t cl = *(const uint32_t*)(crow + cidx + 2 * t);
            uint32_t ch = *(const uint32_t*)(crow + cidx + 8 + 2 * t);
            uint32_t A0[4], A1[4], rr[4];
            ldsm_x4(A0, abase[buf] + (uint32_t)((m0 * ASTR + kk) * 2) + aoff);
            ldsm_x4(A1, abase[buf] + (uint32_t)(((m0 + 16) * ASTR + kk) * 2) + aoff);
            A0[0] = hmul2u(A0[0], cl); A0[1] = hmul2u(A0[1], cl);
            A0[2] = hmul2u(A0[2], ch); A0[3] = hmul2u(A0[3], ch);
            A1[0] = hmul2u(A1[0], cl); A1[1] = hmul2u(A1[1], cl);
            A1[2] = hmul2u(A1[2], ch); A1[3] = hmul2u(A1[3], ch);
            #pragma unroll
            for (int i = 0; i < 4; i++) {
                ldsm_x4_t(rr, bbase[buf] + (uint32_t)((kk * BSTR + n0 + i * 16) * 2) + boff);
                mma16816(acc[2 * i],     A0[0], A0[1], A0[2], A0[3], rr[0], rr[1]);
                mma16816(acc[2 * i + 1], A0[0], A0[1], A0[2], A0[3], rr[2], rr[3]);
                mma16816(acc[8 + 2 * i],     A1[0], A1[1], A1[2], A1[3], rr[0], rr[1]);
                mma16816(acc[8 + 2 * i + 1], A1[0], A1[1], A1[2], A1[3], rr[2], rr[3]);
            }
        }
        if (s + 2 < NSTG) cp_wait1(); else cp_wait0();
        __syncthreads();
    }

    size_t base = (size_t)blockIdx.y * JJ * BB;
    #pragma unroll
    for (int mb = 0; mb < 2; mb++) {
        int j = j0 + m0 + mb * 16 + g;
        #pragma unroll
        for (int nb = 0; nb < 8; nb++) {
            float* a = acc[mb * 8 + nb];
            int b = n0 + nb * 8 + 2 * t;
            *(__half2*)&d_spart[base + (size_t)j * BB + b] = __floats2half2_rn(a[0], a[1]);
            *(__half2*)&d_spart[base + (size_t)(j + 8) * BB + b] = __floats2half2_rn(a[2], a[3]);
        }
    }
}

// ---------------------------------------------------------------------------
// squash: grid (32 s, 8 b-chunks of 32). 512 threads = 32 b x 16 split-groups.
__global__ void __launch_bounds__(512) k_squash(float* __restrict__ out, int final_it) {
    __shared__ float red[16][NU][33];
    int s = blockIdx.x;
    int bl = threadIdx.x & 31, h = threadIdx.x >> 5;   // h = 0..15
    int b = blockIdx.y * 32 + bl;
    #pragma unroll
    for (int u = 0; u < NU; u++) {
        size_t base = (size_t)(u * 32 + s) * BB + b;
        float v = 0.f;
        #pragma unroll
        for (int p = 0; p < 3; p++)
            v += __half2float(d_spart[(size_t)(h + p * 16) * JJ * BB + base]);
        red[h][u][bl] = v;
    }
    __syncthreads();
    if (h == 0) {
        float sv[NU], q = 0.f;
        #pragma unroll
        for (int u = 0; u < NU; u++) {
            float v = 0.f;
            #pragma unroll
            for (int hh = 0; hh < 16; hh++) v += red[hh][u][bl];
            sv[u] = v;
            q = fmaf(v, v, q);
        }
        float mag = sqrtf(q);
        float f = q / ((1.f + q) * mag);
        #pragma unroll
        for (int u = 0; u < NU; u++) {
            float v = sv[u] * f;
            int j = u * 32 + s;
            if (final_it) out[b * JJ + j] = v;
            else          d_vh[j * BB + b] = __float2half(v);
        }
    }
}

// ---------------------------------------------------------------------------
// G2: A2[c,u] += sum_j W[j,k'] * (sum_b vh[j,b]*x[k',b]).
// grid (144 k'-tiles of 128, 2 b-halves). 8 warps (2j x 4k'), acc[4][4].
// W epilogue loads prefetched at u-loop head (overlap with MMA loop).
__global__ void __launch_bounds__(256, 3) k_g2() {
    extern __shared__ __align__(16) __half sm2[];
    __half* xs = sm2;                      // [128][BSTR2]
    __half* vs = sm2 + 128 * BSTR2;        // [2][32][BSTR2]

    const int tid = threadIdx.x, warp = tid >> 5, lane = tid & 31;
    const int wm = warp >> 2, wn = warp & 3;
    const int lt = lane >> 3, lr = lane & 7;
    const int g = lane >> 2, t = lane & 3;
    const int kp0 = blockIdx.x * 128;
    const int b0 = blockIdx.y * 128;
    const int cb = kp0 % CC;

    const uint32_t xbase = cvta_s(xs);
    uint32_t vbase[2] = {cvta_s(vs), cvta_s(vs + 32 * BSTR2)};

    auto issueV = [&](int u, int buf) {
        #pragma unroll
        for (int i = 0; i < 2; i++) {
            int idx = tid + i * 256;
            int r = idx >> 4, seg = idx & 15;
            cp16(vbase[buf] + (uint32_t)((r * BSTR2 + seg * 8) * 2),
                 d_vh + (size_t)(u * 32 + r) * BB + b0 + seg * 8);
        }
        cp_commit();
    };

    #pragma unroll
    for (int i = 0; i < 8; i++) {
        int idx = tid + i * 256;
        int r = idx >> 4, seg = idx & 15;
        cp16(xbase + (uint32_t)((r * BSTR2 + seg * 8) * 2),
             d_xhT + (size_t)(kp0 + r) * BB + b0 + seg * 8);
    }
    issueV(0, 0);
    cp_wait0();
    __syncthreads();

    const uint32_t aoff = (uint32_t)(((wm * 16 + (lt & 1) * 8 + lr) * BSTR2 + (lt >> 1) * 8) * 2);
    const uint32_t boffc = (uint32_t)((((lt >> 1) * 8 + lr) * BSTR2 + (lt & 1) * 8) * 2);

    for (int u = 0; u < NU; u++) {
        int buf = u & 1;
        if (u + 1 < NU) issueV(u + 1, buf ^ 1);

        // ---- prefetch epilogue W (in flight across the MMA loop) ----
        const __half* wrow = d_WTh + (size_t)(u * 32 + wm * 16 + g) * K1;
        uint32_t wpre[8];
        #pragma unroll
        for (int nb = 0; nb < 4; nb++) {
            int kc = kp0 + wn * 32 + nb * 8 + 2 * t;
            wpre[2 * nb]     = *(const uint32_t*)(wrow + kc);
            wpre[2 * nb + 1] = *(const uint32_t*)(wrow + 8 * (size_t)K1 + kc);
        }

        float acc[4][4];
        #pragma unroll
        for (int nb = 0; nb < 4; nb++)
            #pragma unroll
            for (int q = 0; q < 4; q++) acc[nb][q] = 0.f;

        #pragma unroll
        for (int kk = 0; kk < 128; kk += 16) {
            uint32_t A[4], rr[4];
            ldsm_x4(A, vbase[buf] + (uint32_t)(kk * 2) + aoff);
            #pragma unroll
            for (int q = 0; q < 2; q++) {
                ldsm_x4(rr, xbase + (uint32_t)(((wn * 32 + q * 16) * BSTR2 + kk) * 2) + boffc);
                mma16816(acc[2 * q],     A[0], A[1], A[2], A[3], rr[0], rr[1]);
                mma16816(acc[2 * q + 1], A[0], A[1], A[2], A[3], rr[2], rr[3]);
            }
        }

        #pragma unroll
        for (int nb = 0; nb < 4; nb++) {
            float2 w0 = __half22float2(*reinterpret_cast<__half2*>(&wpre[2 * nb]));
            float2 w1 = __half22float2(*reinterpret_cast<__half2*>(&wpre[2 * nb + 1]));
            float p0 = acc[nb][0] * w0.x + acc[nb][2] * w1.x;
            float p1 = acc[nb][1] * w0.y + acc[nb][3] * w1.y;
            #pragma unroll
            for (int m = 4; m <= 16; m <<= 1) {
                p0 += __shfl_xor_sync(0xffffffffu, p0, m);
                p1 += __shfl_xor_sync(0xffffffffu, p1, m);
            }
            if (g == 0) {
                int cc = cb + wn * 32 + nb * 8 + 2 * t;
                atomicAdd(&d_A2[cc * NU + u], p0);
                atomicAdd(&d_A2[(cc + 1) * NU + u], p1);
            }
        }
        if (u + 1 < NU) cp_wait0();
        __syncthreads();
    }
}

// ---------------------------------------------------------------------------
__global__ void k_bupd() {
    int c = blockIdx.x * blockDim.x + threadIdx.x;
    if (c >= CC) return;
    float bv[NU], m = -1e30f;
    #pragma unroll
    for (int u = 0; u < NU; u++) {
        float a = d_A2[c * NU + u];
        d_A2[c * NU + u] = 0.f;
        float nb = d_bij[c * NU + u] + a * (1.f / BB);
        d_bij[c * NU + u] = nb;
        bv[u] = nb;
        m = fmaxf(m, nb);
    }
    float den = 0.f;
    #pragma unroll
    for (int u = 0; u < NU; u++) { bv[u] = expf(bv[u] - m); den += bv[u]; }
    float inv = 1.f / den;
    #pragma unroll
    for (int u = 0; u < NU; u++) d_cijh[u * CC + c] = __float2half(bv[u] * inv);
}

// ---------------------------------------------------------------------------
#define G1_SMEM ((G1STG * 64 * ASTR + G1STG * 32 * BSTR) * 2)   // 66048
#define G2_SMEM ((128 * BSTR2 + 64 * BSTR2) * 2)                // 52224

extern "C" void kernel_launch(void* const* d_in, const int* in_sizes, int n_in,
                              void* d_out, int out_size) {
    const float* x = (const float*)d_in[0];
    const float* W = (const float*)d_in[1];
    if (n_in >= 2 && in_sizes[0] == CC * NU * SS * 16 && in_sizes[1] == BB * 16 * CC) {
        const float* tmp = x; x = W; W = tmp;
    }
    float* out = (float*)d_out;

    static int attr_done = 0;
    if (!attr_done) {
        cudaFuncSetAttribute(k_g1, cudaFuncAttributeMaxDynamicSharedMemorySize, G1_SMEM);
        cudaFuncSetAttribute(k_g2, cudaFuncAttributeMaxDynamicSharedMemorySize, G2_SMEM);
        attr_done = 1;
    }

    k_prep<<<PREP_XBLKS + PREP_WBLKS, dim3(32, 8)>>>(x, W);

    for (int it = 0; it < 3; it++) {
        k_g1<<<dim3(5, SPLIT), 256, G1_SMEM>>>();
        k_squash<<<dim3(SS, 8), 512>>>(out, it == 2);
        if (it < 2) {
            k_g2<<<dim3(K1 / 128, 2), 256, G2_SMEM>>>();
            k_bupd<<<(CC + 255) / 256, 256>>>();
        }
    }
}

// round 15
// speedup vs baseline: 1.4623x; 1.0675x over previous
#include <cuda_runtime.h>
#include <cuda_fp16.h>
#include <stdint.h>

// CapsuleLayer dynamic routing: recompute architecture, pipelined HMMA GEMMs.
// B=256, I=16, C=1152, U=10, S=32, J=320, K1=18432, 3 iterations.
// R15 = R14 (131.1us) + g2 W-tile staged through smem (kills 8-way LDG wavefronts).

#define BB   256
#define CC   1152
#define NU   10
#define SS   32
#define JJ   320
#define K1   18432
#define SPLIT 48
#define KCHUNK 384          // K1/SPLIT
#define NSTG  12            // KCHUNK/32
#define G1STG 3             // pipeline depth
#define ASTR  40            // A smem stride (halfs)
#define BSTR  264           // B smem stride (halfs)
#define BSTR2 136           // G2 smem stride (halfs)

// ---- static device scratch ----
__device__ __half d_xhT[(size_t)K1 * BB];            // 9.4 MB  [k][b]
__device__ __half d_WTh[(size_t)JJ * K1];            // 11.8 MB [j][k] fp16, k=i*1152+c
__device__ __half d_spart[(size_t)SPLIT * JJ * BB];  // 7.9 MB fp16
__device__ __half d_vh [JJ * BB];                    // [j][b]
__device__ float  d_bij[CC * NU];
__device__ __half d_cijh[NU * CC];                   // [u][c] fp16
__device__ float  d_A2 [CC * NU];

// ---- helpers ----
__device__ __forceinline__ void mma16816(float* d, uint32_t a0, uint32_t a1,
                                         uint32_t a2, uint32_t a3,
                                         uint32_t b0, uint32_t b1) {
    asm volatile(
        "mma.sync.aligned.m16n8k16.row.col.f32.f16.f16.f32 "
        "{%0,%1,%2,%3},{%4,%5,%6,%7},{%8,%9},{%0,%1,%2,%3};"
        : "+f"(d[0]), "+f"(d[1]), "+f"(d[2]), "+f"(d[3])
        : "r"(a0), "r"(a1), "r"(a2), "r"(a3), "r"(b0), "r"(b1));
}
__device__ __forceinline__ uint32_t cvta_s(const void* p) {
    return (uint32_t)__cvta_generic_to_shared(p);
}
__device__ __forceinline__ void ldsm_x4(uint32_t* r, uint32_t addr) {
    asm volatile("ldmatrix.sync.aligned.m8n8.x4.shared.b16 {%0,%1,%2,%3},[%4];"
                 : "=r"(r[0]), "=r"(r[1]), "=r"(r[2]), "=r"(r[3]) : "r"(addr));
}
__device__ __forceinline__ void ldsm_x4_t(uint32_t* r, uint32_t addr) {
    asm volatile("ldmatrix.sync.aligned.m8n8.x4.trans.shared.b16 {%0,%1,%2,%3},[%4];"
                 : "=r"(r[0]), "=r"(r[1]), "=r"(r[2]), "=r"(r[3]) : "r"(addr));
}
__device__ __forceinline__ uint32_t h2u(__half2 h) {
    return *reinterpret_cast<uint32_t*>(&h);
}
__device__ __forceinline__ uint32_t hmul2u(uint32_t a, uint32_t b) {
    __half2 r = __hmul2(*reinterpret_cast<__half2*>(&a), *reinterpret_cast<__half2*>(&b));
    return h2u(r);
}
__device__ __forceinline__ void cp16(uint32_t dst, const void* src) {
    asm volatile("cp.async.cg.shared.global [%0], [%1], 16;" :: "r"(dst), "l"(src));
}
__device__ __forceinline__ void cp_commit() { asm volatile("cp.async.commit_group;"); }
__device__ __forceinline__ void cp_wait0() { asm volatile("cp.async.wait_group 0;"); }
__device__ __forceinline__ void cp_wait1() { asm volatile("cp.async.wait_group 1;"); }

// ---------------------------------------------------------------------------
// merged prep: blocks [0, 4608) transpose x; [4608, 10368) transpose W.
// block 0 also inits routing state.
#define PREP_XBLKS (576 * 8)
#define PREP_WBLKS (160 * 36)
__global__ void k_prep(const float* __restrict__ x, const float* __restrict__ W) {
    __shared__ float t32[32][33];
    int tx = threadIdx.x, ty = threadIdx.y;
    int id = blockIdx.x;
    if (id == 0) {
        int tid = ty * 32 + tx;
        for (int t = tid; t < CC * NU; t += 256) {
            d_bij[t] = 0.f; d_A2[t] = 0.f;
            d_cijh[t] = __float2half(0.1f);
        }
    }
    if (id < PREP_XBLKS) {
        int k0 = (id % 576) * 32, b0 = (id / 576) * 32;
        #pragma unroll
        for (int i = 0; i < 4; i++)
            t32[ty + i * 8][tx] = x[(size_t)(b0 + ty + i * 8) * K1 + k0 + tx];
        __syncthreads();
        #pragma unroll
        for (int i = 0; i < 4; i++) {
            int k = k0 + ty + i * 8;
            d_xhT[(size_t)k * BB + b0 + tx] = __float2half(t32[tx][ty + i * 8]);
        }
    } else {
        int wid2 = id - PREP_XBLKS;
        int m0 = (wid2 % 160) * 32, c0 = (wid2 / 160) * 32;
        #pragma unroll
        for (int i = 0; i < 4; i++)
            t32[ty + i * 8][tx] = W[(size_t)(c0 + ty + i * 8) * 5120 + m0 + tx];
        __syncthreads();
        #pragma unroll
        for (int i = 0; i < 4; i++) {
            int m = m0 + ty + i * 8;
            int j = m >> 4, ii = m & 15;
            d_WTh[(size_t)j * K1 + ii * CC + c0 + tx] = __float2half(t32[tx][ty + i * 8]);
        }
    }
}

// ---------------------------------------------------------------------------
// G1: spart[p][j][b] = sum_{k chunk} (cij[u(j),c(k)]*W[j,k]) * x[b,k]
// grid (5 j-tiles of 64, 48 splits) = 240 blocks, 2 CTA/SM.
__global__ void __launch_bounds__(256, 2) k_g1() {
    extern __shared__ __align__(16) __half sm1[];
    __half* a_s = sm1;                         // [G1STG][64*ASTR]
    __half* b_s = sm1 + G1STG * 64 * ASTR;     // [G1STG][32*BSTR]

    const int tid = threadIdx.x;
    const int j0 = blockIdx.x * 64;
    const int kbase = blockIdx.y * KCHUNK;
    const int warp = tid >> 5, lane = tid & 31;
    const int wm = warp >> 2, wn = warp & 3;
    const int m0 = wm * 32, n0 = wn * 64;
    const int lt = lane >> 3, lr = lane & 7;
    const int g = lane >> 2, t = lane & 3;

    const int u_w = (j0 >> 5) + wm;
    const __half* crow = d_cijh + u_w * CC;
    const int c0base = kbase % CC;

    const int ar = tid >> 2, aq = tid & 3;
    const __half* wrow = d_WTh + (size_t)(j0 + ar) * K1;

    const uint32_t aoff = (uint32_t)((((lt & 1) * 8 + lr) * ASTR + (lt >> 1) * 8) * 2);
    const uint32_t boff = (uint32_t)((((lt & 1) * 8 + lr) * BSTR + (lt >> 1) * 8) * 2);
    uint32_t abase[G1STG], bbase[G1STG];
    #pragma unroll
    for (int i = 0; i < G1STG; i++) {
        abase[i] = cvta_s(a_s + i * 64 * ASTR);
        bbase[i] = cvta_s(b_s + i * 32 * BSTR);
    }

    float acc[16][4];
    #pragma unroll
    for (int nb = 0; nb < 16; nb++)
        #pragma unroll
        for (int q = 0; q < 4; q++) acc[nb][q] = 0.f;

    auto issue = [&](int s) {
        int k0 = kbase + s * 32;
        int buf = s % G1STG;
        cp16(abase[buf] + (uint32_t)((ar * ASTR + aq * 8) * 2), wrow + k0 + aq * 8);
        #pragma unroll
        for (int i = 0; i < 4; i++) {
            int idx = tid + i * 256;
            int r = idx >> 5, seg = idx & 31;
            cp16(bbase[buf] + (uint32_t)((r * BSTR + seg * 8) * 2),
                 d_xhT + (size_t)(k0 + r) * BB + seg * 8);
        }
        cp_commit();
    };

    issue(0);
    issue(1);
    cp_wait1();
    __syncthreads();

    for (int s = 0; s < NSTG; s++) {
        int buf = s % G1STG;
        if (s + 2 < NSTG) issue(s + 2);

        #pragma unroll
        for (int kk = 0; kk < 32; kk += 16) {
            int cidx = c0base + s * 32 + kk;
            uint32_t cl = *(const uint32_t*)(crow + cidx + 2 * t);
            uint32_t ch = *(const uint32_t*)(crow + cidx + 8 + 2 * t);
            uint32_t A0[4], A1[4], rr[4];
            ldsm_x4(A0, abase[buf] + (uint32_t)((m0 * ASTR + kk) * 2) + aoff);
            ldsm_x4(A1, abase[buf] + (uint32_t)(((m0 + 16) * ASTR + kk) * 2) + aoff);
            A0[0] = hmul2u(A0[0], cl); A0[1] = hmul2u(A0[1], cl);
            A0[2] = hmul2u(A0[2], ch); A0[3] = hmul2u(A0[3], ch);
            A1[0] = hmul2u(A1[0], cl); A1[1] = hmul2u(A1[1], cl);
            A1[2] = hmul2u(A1[2], ch); A1[3] = hmul2u(A1[3], ch);
            #pragma unroll
            for (int i = 0; i < 4; i++) {
                ldsm_x4_t(rr, bbase[buf] + (uint32_t)((kk * BSTR + n0 + i * 16) * 2) + boff);
                mma16816(acc[2 * i],     A0[0], A0[1], A0[2], A0[3], rr[0], rr[1]);
                mma16816(acc[2 * i + 1], A0[0], A0[1], A0[2], A0[3], rr[2], rr[3]);
                mma16816(acc[8 + 2 * i],     A1[0], A1[1], A1[2], A1[3], rr[0], rr[1]);
                mma16816(acc[8 + 2 * i + 1], A1[0], A1[1], A1[2], A1[3], rr[2], rr[3]);
            }
        }
        if (s + 2 < NSTG) cp_wait1(); else cp_wait0();
        __syncthreads();
    }

    size_t base = (size_t)blockIdx.y * JJ * BB;
    #pragma unroll
    for (int mb = 0; mb < 2; mb++) {
        int j = j0 + m0 + mb * 16 + g;
        #pragma unroll
        for (int nb = 0; nb < 8; nb++) {
            float* a = acc[mb * 8 + nb];
            int b = n0 + nb * 8 + 2 * t;
            *(__half2*)&d_spart[base + (size_t)j * BB + b] = __floats2half2_rn(a[0], a[1]);
            *(__half2*)&d_spart[base + (size_t)(j + 8) * BB + b] = __floats2half2_rn(a[2], a[3]);
        }
    }
}

// ---------------------------------------------------------------------------
// squash: grid (32 s, 8 b-chunks of 32). 512 threads = 32 b x 16 split-groups.
__global__ void __launch_bounds__(512) k_squash(float* __restrict__ out, int final_it) {
    __shared__ float red[16][NU][33];
    int s = blockIdx.x;
    int bl = threadIdx.x & 31, h = threadIdx.x >> 5;   // h = 0..15
    int b = blockIdx.y * 32 + bl;
    #pragma unroll
    for (int u = 0; u < NU; u++) {
        size_t base = (size_t)(u * 32 + s) * BB + b;
        float v = 0.f;
        #pragma unroll
        for (int p = 0; p < 3; p++)
            v += __half2float(d_spart[(size_t)(h + p * 16) * JJ * BB + base]);
        red[h][u][bl] = v;
    }
    __syncthreads();
    if (h == 0) {
        float sv[NU], q = 0.f;
        #pragma unroll
        for (int u = 0; u < NU; u++) {
            float v = 0.f;
            #pragma unroll
            for (int hh = 0; hh < 16; hh++) v += red[hh][u][bl];
            sv[u] = v;
            q = fmaf(v, v, q);
        }
        float mag = sqrtf(q);
        float f = q / ((1.f + q) * mag);
        #pragma unroll
        for (int u = 0; u < NU; u++) {
            float v = sv[u] * f;
            int j = u * 32 + s;
            if (final_it) out[b * JJ + j] = v;
            else          d_vh[j * BB + b] = __float2half(v);
        }
    }
}

// ---------------------------------------------------------------------------
// G2: A2[c,u] += sum_j W[j,k'] * (sum_b vh[j,b]*x[k',b]).
// grid (144 k'-tiles of 128, 2 b-halves). 8 warps (2j x 4k'), acc[4][4].
// vs AND the per-u W tile double-buffered through smem (coalesced cp.async).
__global__ void __launch_bounds__(256, 3) k_g2() {
    extern __shared__ __align__(16) __half sm2[];
    __half* xs = sm2;                      // [128][BSTR2]
    __half* vs = sm2 + 128 * BSTR2;        // [2][32][BSTR2]
    __half* ws = sm2 + 192 * BSTR2;        // [2][32][BSTR2]

    const int tid = threadIdx.x, warp = tid >> 5, lane = tid & 31;
    const int wm = warp >> 2, wn = warp & 3;
    const int lt = lane >> 3, lr = lane & 7;
    const int g = lane >> 2, t = lane & 3;
    const int kp0 = blockIdx.x * 128;
    const int b0 = blockIdx.y * 128;
    const int cb = kp0 % CC;

    const uint32_t xbase = cvta_s(xs);
    uint32_t vbase[2] = {cvta_s(vs), cvta_s(vs + 32 * BSTR2)};
    uint32_t wbase[2] = {cvta_s(ws), cvta_s(ws + 32 * BSTR2)};

    // per-u staging: vs (32 rows x 256 halfs of vh slice) + ws (32 rows x 128 halfs of W)
    auto issueUV = [&](int u, int buf) {
        #pragma unroll
        for (int i = 0; i < 2; i++) {
            int idx = tid + i * 256;
            int r = idx >> 4, seg = idx & 15;
            cp16(vbase[buf] + (uint32_t)((r * BSTR2 + seg * 8) * 2),
                 d_vh + (size_t)(u * 32 + r) * BB + b0 + seg * 8);
            cp16(wbase[buf] + (uint32_t)((r * BSTR2 + seg * 8) * 2),
                 d_WTh + (size_t)(u * 32 + r) * K1 + kp0 + seg * 8);
        }
        cp_commit();
    };

    #pragma unroll
    for (int i = 0; i < 8; i++) {
        int idx = tid + i * 256;
        int r = idx >> 4, seg = idx & 15;
        cp16(xbase + (uint32_t)((r * BSTR2 + seg * 8) * 2),
             d_xhT + (size_t)(kp0 + r) * BB + b0 + seg * 8);
    }
    issueUV(0, 0);
    cp_wait0();
    __syncthreads();

    const uint32_t aoff = (uint32_t)(((wm * 16 + (lt & 1) * 8 + lr) * BSTR2 + (lt >> 1) * 8) * 2);
    const uint32_t boffc = (uint32_t)((((lt >> 1) * 8 + lr) * BSTR2 + (lt & 1) * 8) * 2);

    for (int u = 0; u < NU; u++) {
        int buf = u & 1;
        if (u + 1 < NU) issueUV(u + 1, buf ^ 1);

        float acc[4][4];
        #pragma unroll
        for (int nb = 0; nb < 4; nb++)
            #pragma unroll
            for (int q = 0; q < 4; q++) acc[nb][q] = 0.f;

        #pragma unroll
        for (int kk = 0; kk < 128; kk += 16) {
            uint32_t A[4], rr[4];
            ldsm_x4(A, vbase[buf] + (uint32_t)(kk * 2) + aoff);
            #pragma unroll
            for (int q = 0; q < 2; q++) {
                ldsm_x4(rr, xbase + (uint32_t)(((wn * 32 + q * 16) * BSTR2 + kk) * 2) + boffc);
                mma16816(acc[2 * q],     A[0], A[1], A[2], A[3], rr[0], rr[1]);
                mma16816(acc[2 * q + 1], A[0], A[1], A[2], A[3], rr[2], rr[3]);
            }
        }

        // epilogue: W from smem (LDS, ~2-way conflicts vs 8-way LDG wavefronts)
        const __half* wsl = ws + (size_t)buf * 32 * BSTR2;
        #pragma unroll
        for (int nb = 0; nb < 4; nb++) {
            int col = wn * 32 + nb * 8 + 2 * t;
            float2 w0 = __half22float2(*(const __half2*)&wsl[(wm * 16 + g) * BSTR2 + col]);
            float2 w1 = __half22float2(*(const __half2*)&wsl[(wm * 16 + g + 8) * BSTR2 + col]);
            float p0 = acc[nb][0] * w0.x + acc[nb][2] * w1.x;
            float p1 = acc[nb][1] * w0.y + acc[nb][3] * w1.y;
            #pragma unroll
            for (int m = 4; m <= 16; m <<= 1) {
                p0 += __shfl_xor_sync(0xffffffffu, p0, m);
                p1 += __shfl_xor_sync(0xffffffffu, p1, m);
            }
            if (g == 0) {
                int cc = cb + wn * 32 + nb * 8 + 2 * t;
                atomicAdd(&d_A2[cc * NU + u], p0);
                atomicAdd(&d_A2[(cc + 1) * NU + u], p1);
            }
        }
        if (u + 1 < NU) cp_wait0();
        __syncthreads();
    }
}

// ---------------------------------------------------------------------------
__global__ void k_bupd() {
    int c = blockIdx.x * blockDim.x + threadIdx.x;
    if (c >= CC) return;
    float bv[NU], m = -1e30f;
    #pragma unroll
    for (int u = 0; u < NU; u++) {
        float a = d_A2[c * NU + u];
        d_A2[c * NU + u] = 0.f;
        float nb = d_bij[c * NU + u] + a * (1.f / BB);
        d_bij[c * NU + u] = nb;
        bv[u] = nb;
        m = fmaxf(m, nb);
    }
    float den = 0.f;
    #pragma unroll
    for (int u = 0; u < NU; u++) { bv[u] = expf(bv[u] - m); den += bv[u]; }
    float inv = 1.f / den;
    #pragma unroll
    for (int u = 0; u < NU; u++) d_cijh[u * CC + c] = __float2half(bv[u] * inv);
}

// ---------------------------------------------------------------------------
#define G1_SMEM ((G1STG * 64 * ASTR + G1STG * 32 * BSTR) * 2)   // 66048
#define G2_SMEM (256 * BSTR2 * 2)                               // 69632

extern "C" void kernel_launch(void* const* d_in, const int* in_sizes, int n_in,
                              void* d_out, int out_size) {
    const float* x = (const float*)d_in[0];
    const float* W = (const float*)d_in[1];
    if (n_in >= 2 && in_sizes[0] == CC * NU * SS * 16 && in_sizes[1] == BB * 16 * CC) {
        const float* tmp = x; x = W; W = tmp;
    }
    float* out = (float*)d_out;

    static int attr_done = 0;
    if (!attr_done) {
        cudaFuncSetAttribute(k_g1, cudaFuncAttributeMaxDynamicSharedMemorySize, G1_SMEM);
        cudaFuncSetAttribute(k_g2, cudaFuncAttributeMaxDynamicSharedMemorySize, G2_SMEM);
        attr_done = 1;
    }

    k_prep<<<PREP_XBLKS + PREP_WBLKS, dim3(32, 8)>>>(x, W);

    for (int it = 0; it < 3; it++) {
        k_g1<<<dim3(5, SPLIT), 256, G1_SMEM>>>();
        k_squash<<<dim3(SS, 8), 512>>>(out, it == 2);
        if (it < 2) {
            k_g2<<<dim3(K1 / 128, 2), 256, G2_SMEM>>>();
            k_bupd<<<(CC + 255) / 256, 256>>>();
        }
    }
}